// round 13
// baseline (speedup 1.0000x reference)
#include <cuda_runtime.h>
#include <float.h>
#include <stdint.h>

// Problem constants (fixed shapes)
#define N_A   100000
#define N_M   50000
#define N_TOT (N_A + N_M)
#define E_AA  600000
#define E_AM  400000
#define E_TOT (E_AA + E_AM)
#define DIM   128
#define NHEAD 4
#define NEG_SLOPE 0.2f
#define TILE_R 64

// ---------------- scratch (device globals) -----------------------------------
__device__ float g_xl [N_A * DIM];     // x_asset @ Wl1
__device__ float g_xra[N_A * DIM];     // x_asset @ Wr1
__device__ float g_xrm[N_M * DIM];     // x_market @ Wr1
__device__ int   g_deg   [N_TOT];
__device__ int   g_rowptr[N_TOT];
__device__ int   g_cursor[N_TOT];
__device__ int   g_perm  [E_TOT];

// ---------------- f32x2 packed math helpers ----------------------------------
__device__ __forceinline__ unsigned long long pk2(float lo, float hi) {
    unsigned long long r;
    asm("mov.b64 %0, {%1, %2};" : "=l"(r) : "f"(lo), "f"(hi));
    return r;
}
__device__ __forceinline__ void fma2(unsigned long long& d,
                                     unsigned long long a, unsigned long long b) {
    asm("fma.rn.f32x2 %0, %1, %2, %0;" : "+l"(d) : "l"(a), "l"(b));
}
__device__ __forceinline__ void upk2(unsigned long long v, float& lo, float& hi) {
    asm("mov.b64 {%0, %1}, %2;" : "=f"(lo), "=f"(hi) : "l"(v));
}

__device__ __forceinline__ float lrelu(float v) {
    return v > 0.0f ? v : NEG_SLOPE * v;
}

// ================= CSR construction ==========================================
__global__ void k_hist(const int* __restrict__ dst_aa,
                       const int* __restrict__ dst_am,
                       int* __restrict__ deg) {
    int i = blockIdx.x * blockDim.x + threadIdx.x;
    if (i < E_AA)            atomicAdd(&deg[dst_aa[i]], 1);
    else if (i < E_TOT)      atomicAdd(&deg[N_A + dst_am[i - E_AA]], 1);
}

// Single-block exclusive scan, 16 ints/thread -> 16384 per chunk, 10 chunks.
__global__ void __launch_bounds__(1024, 1)
k_scan(const int* __restrict__ deg, int* __restrict__ rowptr,
       int* __restrict__ cursor) {
    __shared__ int warpsums[32];
    __shared__ int s_carry;
    int lane = threadIdx.x & 31, wid = threadIdx.x >> 5;
    if (threadIdx.x == 0) s_carry = 0;
    __syncthreads();

    for (int base = 0; base < N_TOT; base += 16384) {
        int idx = base + threadIdx.x * 16;
        int v[16];
        if (idx + 15 < N_TOT) {
#pragma unroll
            for (int q = 0; q < 4; ++q) {
                int4 t = *(const int4*)&deg[idx + q * 4];
                v[q * 4] = t.x; v[q * 4 + 1] = t.y;
                v[q * 4 + 2] = t.z; v[q * 4 + 3] = t.w;
            }
        } else {
#pragma unroll
            for (int q = 0; q < 16; ++q)
                v[q] = (idx + q < N_TOT) ? deg[idx + q] : 0;
        }
        int pre[16];
        int run = 0;
#pragma unroll
        for (int q = 0; q < 16; ++q) { run += v[q]; pre[q] = run; }
        int tsum = run;

        int x = tsum;
#pragma unroll
        for (int o = 1; o < 32; o <<= 1) {
            int y = __shfl_up_sync(0xffffffffu, x, o);
            if (lane >= o) x += y;
        }
        if (lane == 31) warpsums[wid] = x;
        __syncthreads();
        if (wid == 0) {
            int w = warpsums[lane];
#pragma unroll
            for (int o = 1; o < 32; o <<= 1) {
                int y = __shfl_up_sync(0xffffffffu, w, o);
                if (lane >= o) w += y;
            }
            warpsums[lane] = w;
        }
        __syncthreads();

        int carry = s_carry;
        int excl = carry + (wid ? warpsums[wid - 1] : 0) + (x - tsum);
        if (idx + 15 < N_TOT) {
#pragma unroll
            for (int q = 0; q < 4; ++q) {
                int4 o;
                o.x = excl + (q * 4     ? pre[q * 4 - 1] : 0);
                o.y = excl + pre[q * 4];
                o.z = excl + pre[q * 4 + 1];
                o.w = excl + pre[q * 4 + 2];
                *(int4*)&rowptr[idx + q * 4] = o;
                *(int4*)&cursor[idx + q * 4] = o;
            }
        } else {
#pragma unroll
            for (int q = 0; q < 16; ++q) {
                if (idx + q < N_TOT) {
                    int e = excl + (q ? pre[q - 1] : 0);
                    rowptr[idx + q] = e;
                    cursor[idx + q] = e;
                }
            }
        }
        __syncthreads();
        if (threadIdx.x == 0) s_carry = carry + warpsums[31];
        __syncthreads();
    }
}

__global__ void k_scatter(const int* __restrict__ src_aa, const int* __restrict__ dst_aa,
                          const int* __restrict__ src_am, const int* __restrict__ dst_am,
                          int* __restrict__ cursor, int* __restrict__ perm) {
    int i = blockIdx.x * blockDim.x + threadIdx.x;
    if (i < E_AA) {
        int d = dst_aa[i];
        int slot = atomicAdd(&cursor[d], 1);
        perm[slot] = src_aa[i];
    } else if (i < E_TOT) {
        int j = i - E_AA;
        int d = N_A + dst_am[j];
        int slot = atomicAdd(&cursor[d], 1);
        perm[slot] = src_am[j];
    }
}

// ================= GEMMs (R8 configuration — measured best) ===================
#define SMEM_DUAL   ((2 * DIM * DIM + TILE_R * DIM) * (int)sizeof(float))  // 163840
#define SMEM_SINGLE ((DIM * DIM + TILE_R * DIM) * (int)sizeof(float))      //  98304

__global__ void __launch_bounds__(512, 1)
k_gemm_dual(const float* __restrict__ X,
            const float* __restrict__ Wl,
            const float* __restrict__ Wr,
            float* __restrict__ Yl,
            float* __restrict__ Yr,
            int nrows) {
    extern __shared__ float sm[];
    float* wls = sm;                 // [128][128]
    float* wrs = sm + DIM * DIM;
    float* xs  = sm + 2 * DIM * DIM; // [64][128]

    for (int i = threadIdx.x; i < DIM * DIM / 4; i += blockDim.x) {
        ((float4*)wls)[i] = ((const float4*)Wl)[i];
        ((float4*)wrs)[i] = ((const float4*)Wr)[i];
    }

    int lane = threadIdx.x & 31;
    int wid  = threadIdx.x >> 5;
    int half = wid >> 3;             // 0: Wl, 1: Wr
    int rg   = wid & 7;

    const float* ws = half ? wrs : wls;
    float*       Y  = half ? Yr  : Yl;

    int ntiles = (nrows + TILE_R - 1) / TILE_R;
    for (int t = blockIdx.x; t < ntiles; t += gridDim.x) {
        int tile = t * TILE_R;
        __syncthreads();
        for (int i = threadIdx.x; i < TILE_R * DIM / 4; i += blockDim.x) {
            int row = i >> 5;
            float4 v = make_float4(0.f, 0.f, 0.f, 0.f);
            if (tile + row < nrows)
                v = ((const float4*)X)[(tile + row) * 32 + (i & 31)];
            ((float4*)xs)[i] = v;
        }
        __syncthreads();

        unsigned long long acc[8][2];
#pragma unroll
        for (int r = 0; r < 8; ++r) { acc[r][0] = 0ull; acc[r][1] = 0ull; }

#pragma unroll 2
        for (int k4 = 0; k4 < DIM; k4 += 4) {
            float4 xa[8];
#pragma unroll
            for (int r = 0; r < 8; ++r)
                xa[r] = *(const float4*)&xs[(rg * 8 + r) * DIM + k4];
#pragma unroll
            for (int kk = 0; kk < 4; ++kk) {
                ulonglong2 wv = *(const ulonglong2*)&ws[(k4 + kk) * DIM + lane * 4];
#pragma unroll
                for (int r = 0; r < 8; ++r) {
                    float x = ((const float*)&xa[r])[kk];
                    unsigned long long xp = pk2(x, x);
                    fma2(acc[r][0], xp, wv.x);
                    fma2(acc[r][1], xp, wv.y);
                }
            }
        }

#pragma unroll
        for (int r = 0; r < 8; ++r) {
            int row = tile + rg * 8 + r;
            if (row < nrows) {
                float4 o;
                upk2(acc[r][0], o.x, o.y);
                upk2(acc[r][1], o.z, o.w);
                *(float4*)&Y[row * DIM + lane * 4] = o;
            }
        }
    }
}

__global__ void __launch_bounds__(256, 2)
k_gemm_single(const float* __restrict__ X,
              const float* __restrict__ W,
              float* __restrict__ Y,
              int nrows) {
    extern __shared__ float sm[];
    float* ws = sm;
    float* xs = sm + DIM * DIM;

    for (int i = threadIdx.x; i < DIM * DIM / 4; i += blockDim.x)
        ((float4*)ws)[i] = ((const float4*)W)[i];

    int lane = threadIdx.x & 31;
    int rg   = threadIdx.x >> 5;

    int ntiles = (nrows + TILE_R - 1) / TILE_R;
    for (int t = blockIdx.x; t < ntiles; t += gridDim.x) {
        int tile = t * TILE_R;
        __syncthreads();
        for (int i = threadIdx.x; i < TILE_R * DIM / 4; i += blockDim.x) {
            int row = i >> 5;
            float4 v = make_float4(0.f, 0.f, 0.f, 0.f);
            if (tile + row < nrows)
                v = ((const float4*)X)[(tile + row) * 32 + (i & 31)];
            ((float4*)xs)[i] = v;
        }
        __syncthreads();

        unsigned long long acc[8][2];
#pragma unroll
        for (int r = 0; r < 8; ++r) { acc[r][0] = 0ull; acc[r][1] = 0ull; }

#pragma unroll 2
        for (int k4 = 0; k4 < DIM; k4 += 4) {
            float4 xa[8];
#pragma unroll
            for (int r = 0; r < 8; ++r)
                xa[r] = *(const float4*)&xs[(rg * 8 + r) * DIM + k4];
#pragma unroll
            for (int kk = 0; kk < 4; ++kk) {
                ulonglong2 wv = *(const ulonglong2*)&ws[(k4 + kk) * DIM + lane * 4];
#pragma unroll
                for (int r = 0; r < 8; ++r) {
                    float x = ((const float*)&xa[r])[kk];
                    unsigned long long xp = pk2(x, x);
                    fma2(acc[r][0], xp, wv.x);
                    fma2(acc[r][1], xp, wv.y);
                }
            }
        }

#pragma unroll
        for (int r = 0; r < 8; ++r) {
            int row = tile + rg * 8 + r;
            if (row < nrows) {
                float4 o;
                upk2(acc[r][0], o.x, o.y);
                upk2(acc[r][1], o.z, o.w);
                *(float4*)&Y[row * DIM + lane * 4] = o;
            }
        }
    }
}

// ================= per-node fused attention + aggregation ====================
// Processes nodes in [node_begin, node_end). One warp per dst node; ILP-2.
__global__ void __launch_bounds__(256)
k_node_agg(const int* __restrict__ rowptr,
           const int* __restrict__ deg,
           const int* __restrict__ perm,
           const float* __restrict__ xl,
           const float* __restrict__ xra,
           const float* __restrict__ xrm,
           const float* __restrict__ att1,
           const float* __restrict__ bias1,
           float* __restrict__ out,
           int node_begin, int node_end) {
    int warp_global = (blockIdx.x * blockDim.x + threadIdx.x) >> 5;
    int lane = threadIdx.x & 31;
    int nwarps = (gridDim.x * blockDim.x) >> 5;

    float4 attv = ((const float4*)att1)[lane];
    float4 bv   = ((const float4*)bias1)[lane];

    for (int node = node_begin + warp_global; node < node_end; node += nwarps) {
        const float* xr = (node < N_A) ? &xra[node * DIM]
                                       : &xrm[(node - N_A) * DIM];
        float4 b = *(const float4*)&xr[lane * 4];

        int start = rowptr[node];
        int len   = deg[node];

        float4 acc = make_float4(0.f, 0.f, 0.f, 0.f);
        float ssum = 0.f;

        for (int base = 0; base < len; base += 32) {
            int e = base + lane;
            int sidx = (e < len) ? perm[start + e] : 0;
            int cnt = min(32, len - base);

            int j = 0;
            for (; j + 2 <= cnt; j += 2) {
                int si0 = __shfl_sync(0xffffffffu, sidx, j);
                int si1 = __shfl_sync(0xffffffffu, sidx, j + 1);
                float4 a0 = *(const float4*)&xl[si0 * DIM + lane * 4];
                float4 a1 = *(const float4*)&xl[si1 * DIM + lane * 4];

                float p0 = lrelu(a0.x + b.x) * attv.x + lrelu(a0.y + b.y) * attv.y
                         + lrelu(a0.z + b.z) * attv.z + lrelu(a0.w + b.w) * attv.w;
                float p1 = lrelu(a1.x + b.x) * attv.x + lrelu(a1.y + b.y) * attv.y
                         + lrelu(a1.z + b.z) * attv.z + lrelu(a1.w + b.w) * attv.w;

                p0 += __shfl_xor_sync(0xffffffffu, p0, 1);
                p1 += __shfl_xor_sync(0xffffffffu, p1, 1);
                p0 += __shfl_xor_sync(0xffffffffu, p0, 2);
                p1 += __shfl_xor_sync(0xffffffffu, p1, 2);
                p0 += __shfl_xor_sync(0xffffffffu, p0, 4);
                p1 += __shfl_xor_sync(0xffffffffu, p1, 4);

                float w0 = __expf(p0);
                float w1 = __expf(p1);

                acc.x = fmaf(w0, a0.x, fmaf(w1, a1.x, acc.x));
                acc.y = fmaf(w0, a0.y, fmaf(w1, a1.y, acc.y));
                acc.z = fmaf(w0, a0.z, fmaf(w1, a1.z, acc.z));
                acc.w = fmaf(w0, a0.w, fmaf(w1, a1.w, acc.w));
                ssum += w0 + w1;
            }
            if (j < cnt) {
                int si = __shfl_sync(0xffffffffu, sidx, j);
                float4 a = *(const float4*)&xl[si * DIM + lane * 4];
                float p = lrelu(a.x + b.x) * attv.x + lrelu(a.y + b.y) * attv.y
                        + lrelu(a.z + b.z) * attv.z + lrelu(a.w + b.w) * attv.w;
                p += __shfl_xor_sync(0xffffffffu, p, 1);
                p += __shfl_xor_sync(0xffffffffu, p, 2);
                p += __shfl_xor_sync(0xffffffffu, p, 4);
                float w = __expf(p);
                acc.x = fmaf(w, a.x, acc.x);
                acc.y = fmaf(w, a.y, acc.y);
                acc.z = fmaf(w, a.z, acc.z);
                acc.w = fmaf(w, a.w, acc.w);
                ssum += w;
            }
        }

        float inv = __frcp_rn(fmaxf(ssum, 1e-16f));
        float4 o = make_float4(fmaf(acc.x, inv, bv.x),
                               fmaf(acc.y, inv, bv.y),
                               fmaf(acc.z, inv, bv.z),
                               fmaf(acc.w, inv, bv.w));
        *(float4*)&out[node * DIM + lane * 4] = o;
    }
}

// ================= host launcher ==============================================
extern "C" void kernel_launch(void* const* d_in, const int* in_sizes, int n_in,
                              void* d_out, int out_size) {
    const float* x_asset  = (const float*)d_in[0];
    const float* x_market = (const float*)d_in[1];
    const int*   edge_aa  = (const int*)d_in[2];
    const int*   edge_am  = (const int*)d_in[3];
    const float* Wl       = (const float*)d_in[4];
    const float* Wr       = (const float*)d_in[5];
    const float* att      = (const float*)d_in[6];
    const float* bias     = (const float*)d_in[7];
    float* out = (float*)d_out;

    // Only the LAST layer matters (x_dict never updated between layers).
    const float* Wl1   = Wl  + DIM * DIM;
    const float* Wr1   = Wr  + DIM * DIM;
    const float* att1  = att + NHEAD * 32;
    const float* bias1 = bias + DIM;

    float *p_xl, *p_xra, *p_xrm;
    int *p_deg, *p_rowptr, *p_cursor, *p_perm;
    cudaGetSymbolAddress((void**)&p_xl,     g_xl);
    cudaGetSymbolAddress((void**)&p_xra,    g_xra);
    cudaGetSymbolAddress((void**)&p_xrm,    g_xrm);
    cudaGetSymbolAddress((void**)&p_deg,    g_deg);
    cudaGetSymbolAddress((void**)&p_rowptr, g_rowptr);
    cudaGetSymbolAddress((void**)&p_cursor, g_cursor);
    cudaGetSymbolAddress((void**)&p_perm,   g_perm);

    cudaFuncSetAttribute(k_gemm_dual,   cudaFuncAttributeMaxDynamicSharedMemorySize, SMEM_DUAL);
    cudaFuncSetAttribute(k_gemm_single, cudaFuncAttributeMaxDynamicSharedMemorySize, SMEM_SINGLE);

    // Lazily-created streams + events (host-side only; identical work each call).
    static cudaStream_t s_csr = nullptr, s_mkt = nullptr;
    static cudaEvent_t ev_fork = nullptr, ev_csr = nullptr,
                       ev_dual = nullptr, ev_mkt = nullptr;
    if (s_csr == nullptr) {
        cudaStreamCreateWithFlags(&s_csr, cudaStreamNonBlocking);
        cudaStreamCreateWithFlags(&s_mkt, cudaStreamNonBlocking);
        cudaEventCreateWithFlags(&ev_fork, cudaEventDisableTiming);
        cudaEventCreateWithFlags(&ev_csr,  cudaEventDisableTiming);
        cudaEventCreateWithFlags(&ev_dual, cudaEventDisableTiming);
        cudaEventCreateWithFlags(&ev_mkt,  cudaEventDisableTiming);
    }

    // --- fork ---
    cudaEventRecord(ev_fork, 0);
    cudaStreamWaitEvent(s_csr, ev_fork, 0);
    cudaStreamWaitEvent(s_mkt, ev_fork, 0);

    // branch 1 (s_csr): CSR build
    cudaMemsetAsync(p_deg, 0, N_TOT * sizeof(int), s_csr);
    k_hist<<<(E_TOT + 255) / 256, 256, 0, s_csr>>>(edge_aa + E_AA,
                                                   edge_am + E_AM, p_deg);
    k_scan<<<1, 1024, 0, s_csr>>>(p_deg, p_rowptr, p_cursor);
    k_scatter<<<(E_TOT + 255) / 256, 256, 0, s_csr>>>(edge_aa, edge_aa + E_AA,
                                                      edge_am, edge_am + E_AM,
                                                      p_cursor, p_perm);
    cudaEventRecord(ev_csr, s_csr);

    // branch 2 (s_mkt): market GEMM (fills dual's tail) -> market aggregation
    k_gemm_single<<<296, 256, SMEM_SINGLE, s_mkt>>>(x_market, Wr1, p_xrm, N_M);

    // branch 0 (main): dual GEMM -> asset aggregation
    k_gemm_dual<<<148, 512, SMEM_DUAL>>>(x_asset, Wl1, Wr1, p_xl, p_xra, N_A);
    cudaEventRecord(ev_dual, 0);

    cudaStreamWaitEvent(0, ev_csr, 0);
    k_node_agg<<<(N_A * 32 + 255) / 256, 256>>>(p_rowptr, p_deg, p_perm,
                                                p_xl, p_xra, p_xrm,
                                                att1, bias1, out,
                                                0, N_A);

    cudaStreamWaitEvent(s_mkt, ev_dual, 0);   // market agg needs xl
    cudaStreamWaitEvent(s_mkt, ev_csr, 0);
    k_node_agg<<<(N_M * 32 + 255) / 256, 256, 0, s_mkt>>>(p_rowptr, p_deg, p_perm,
                                                          p_xl, p_xra, p_xrm,
                                                          att1, bias1, out,
                                                          N_A, N_TOT);
    cudaEventRecord(ev_mkt, s_mkt);

    // --- join onto the capture (main) stream ---
    cudaStreamWaitEvent(0, ev_mkt, 0);
}

// round 14
// speedup vs baseline: 1.1033x; 1.1033x over previous
#include <cuda_runtime.h>
#include <float.h>
#include <stdint.h>

// Problem constants (fixed shapes)
#define N_A   100000
#define N_M   50000
#define N_TOT (N_A + N_M)
#define E_AA  600000
#define E_AM  400000
#define E_TOT (E_AA + E_AM)
#define DIM   128
#define NHEAD 4
#define NEG_SLOPE 0.2f
#define TILE_R 64

// ---------------- scratch (device globals) -----------------------------------
__device__ float g_xl [N_A * DIM];     // x_asset @ Wl1
__device__ float g_xra[N_A * DIM];     // x_asset @ Wr1
__device__ float g_xrm[N_M * DIM];     // x_market @ Wr1
__device__ int   g_deg   [N_TOT];
__device__ int   g_rowptr[N_TOT];
__device__ int   g_cursor[N_TOT];
__device__ int   g_perm  [E_TOT];

// ---------------- f32x2 packed math helpers ----------------------------------
__device__ __forceinline__ unsigned long long pk2(float lo, float hi) {
    unsigned long long r;
    asm("mov.b64 %0, {%1, %2};" : "=l"(r) : "f"(lo), "f"(hi));
    return r;
}
__device__ __forceinline__ void fma2(unsigned long long& d,
                                     unsigned long long a, unsigned long long b) {
    asm("fma.rn.f32x2 %0, %1, %2, %0;" : "+l"(d) : "l"(a), "l"(b));
}
__device__ __forceinline__ void upk2(unsigned long long v, float& lo, float& hi) {
    asm("mov.b64 {%0, %1}, %2;" : "=f"(lo), "=f"(hi) : "l"(v));
}

__device__ __forceinline__ float lrelu(float v) {
    return v > 0.0f ? v : NEG_SLOPE * v;
}

// ================= CSR construction ==========================================
__global__ void k_hist(const int* __restrict__ dst_aa,
                       const int* __restrict__ dst_am,
                       int* __restrict__ deg) {
    int i = blockIdx.x * blockDim.x + threadIdx.x;
    if (i < E_AA)            atomicAdd(&deg[dst_aa[i]], 1);
    else if (i < E_TOT)      atomicAdd(&deg[N_A + dst_am[i - E_AA]], 1);
}

// Single-block exclusive scan, 16 ints/thread -> 16384 per chunk, 10 chunks.
__global__ void __launch_bounds__(1024, 1)
k_scan(const int* __restrict__ deg, int* __restrict__ rowptr,
       int* __restrict__ cursor) {
    __shared__ int warpsums[32];
    __shared__ int s_carry;
    int lane = threadIdx.x & 31, wid = threadIdx.x >> 5;
    if (threadIdx.x == 0) s_carry = 0;
    __syncthreads();

    for (int base = 0; base < N_TOT; base += 16384) {
        int idx = base + threadIdx.x * 16;
        int v[16];
        if (idx + 15 < N_TOT) {
#pragma unroll
            for (int q = 0; q < 4; ++q) {
                int4 t = *(const int4*)&deg[idx + q * 4];
                v[q * 4] = t.x; v[q * 4 + 1] = t.y;
                v[q * 4 + 2] = t.z; v[q * 4 + 3] = t.w;
            }
        } else {
#pragma unroll
            for (int q = 0; q < 16; ++q)
                v[q] = (idx + q < N_TOT) ? deg[idx + q] : 0;
        }
        int pre[16];
        int run = 0;
#pragma unroll
        for (int q = 0; q < 16; ++q) { run += v[q]; pre[q] = run; }
        int tsum = run;

        int x = tsum;
#pragma unroll
        for (int o = 1; o < 32; o <<= 1) {
            int y = __shfl_up_sync(0xffffffffu, x, o);
            if (lane >= o) x += y;
        }
        if (lane == 31) warpsums[wid] = x;
        __syncthreads();
        if (wid == 0) {
            int w = warpsums[lane];
#pragma unroll
            for (int o = 1; o < 32; o <<= 1) {
                int y = __shfl_up_sync(0xffffffffu, w, o);
                if (lane >= o) w += y;
            }
            warpsums[lane] = w;
        }
        __syncthreads();

        int carry = s_carry;
        int excl = carry + (wid ? warpsums[wid - 1] : 0) + (x - tsum);
        if (idx + 15 < N_TOT) {
#pragma unroll
            for (int q = 0; q < 4; ++q) {
                int4 o;
                o.x = excl + (q * 4     ? pre[q * 4 - 1] : 0);
                o.y = excl + pre[q * 4];
                o.z = excl + pre[q * 4 + 1];
                o.w = excl + pre[q * 4 + 2];
                *(int4*)&rowptr[idx + q * 4] = o;
                *(int4*)&cursor[idx + q * 4] = o;
            }
        } else {
#pragma unroll
            for (int q = 0; q < 16; ++q) {
                if (idx + q < N_TOT) {
                    int e = excl + (q ? pre[q - 1] : 0);
                    rowptr[idx + q] = e;
                    cursor[idx + q] = e;
                }
            }
        }
        __syncthreads();
        if (threadIdx.x == 0) s_carry = carry + warpsums[31];
        __syncthreads();
    }
}

__global__ void k_scatter(const int* __restrict__ src_aa, const int* __restrict__ dst_aa,
                          const int* __restrict__ src_am, const int* __restrict__ dst_am,
                          int* __restrict__ cursor, int* __restrict__ perm) {
    int i = blockIdx.x * blockDim.x + threadIdx.x;
    if (i < E_AA) {
        int d = dst_aa[i];
        int slot = atomicAdd(&cursor[d], 1);
        perm[slot] = src_aa[i];
    } else if (i < E_TOT) {
        int j = i - E_AA;
        int d = N_A + dst_am[j];
        int slot = atomicAdd(&cursor[d], 1);
        perm[slot] = src_am[j];
    }
}

// ================= GEMMs (R8 configuration — measured best) ===================
#define SMEM_DUAL   ((2 * DIM * DIM + TILE_R * DIM) * (int)sizeof(float))  // 163840
#define SMEM_SINGLE ((DIM * DIM + TILE_R * DIM) * (int)sizeof(float))      //  98304

__global__ void __launch_bounds__(512, 1)
k_gemm_dual(const float* __restrict__ X,
            const float* __restrict__ Wl,
            const float* __restrict__ Wr,
            float* __restrict__ Yl,
            float* __restrict__ Yr,
            int nrows) {
    extern __shared__ float sm[];
    float* wls = sm;                 // [128][128]
    float* wrs = sm + DIM * DIM;
    float* xs  = sm + 2 * DIM * DIM; // [64][128]

    for (int i = threadIdx.x; i < DIM * DIM / 4; i += blockDim.x) {
        ((float4*)wls)[i] = ((const float4*)Wl)[i];
        ((float4*)wrs)[i] = ((const float4*)Wr)[i];
    }

    int lane = threadIdx.x & 31;
    int wid  = threadIdx.x >> 5;
    int half = wid >> 3;             // 0: Wl, 1: Wr
    int rg   = wid & 7;

    const float* ws = half ? wrs : wls;
    float*       Y  = half ? Yr  : Yl;

    int ntiles = (nrows + TILE_R - 1) / TILE_R;
    for (int t = blockIdx.x; t < ntiles; t += gridDim.x) {
        int tile = t * TILE_R;
        __syncthreads();
        for (int i = threadIdx.x; i < TILE_R * DIM / 4; i += blockDim.x) {
            int row = i >> 5;
            float4 v = make_float4(0.f, 0.f, 0.f, 0.f);
            if (tile + row < nrows)
                v = ((const float4*)X)[(tile + row) * 32 + (i & 31)];
            ((float4*)xs)[i] = v;
        }
        __syncthreads();

        unsigned long long acc[8][2];
#pragma unroll
        for (int r = 0; r < 8; ++r) { acc[r][0] = 0ull; acc[r][1] = 0ull; }

#pragma unroll 2
        for (int k4 = 0; k4 < DIM; k4 += 4) {
            float4 xa[8];
#pragma unroll
            for (int r = 0; r < 8; ++r)
                xa[r] = *(const float4*)&xs[(rg * 8 + r) * DIM + k4];
#pragma unroll
            for (int kk = 0; kk < 4; ++kk) {
                ulonglong2 wv = *(const ulonglong2*)&ws[(k4 + kk) * DIM + lane * 4];
#pragma unroll
                for (int r = 0; r < 8; ++r) {
                    float x = ((const float*)&xa[r])[kk];
                    unsigned long long xp = pk2(x, x);
                    fma2(acc[r][0], xp, wv.x);
                    fma2(acc[r][1], xp, wv.y);
                }
            }
        }

#pragma unroll
        for (int r = 0; r < 8; ++r) {
            int row = tile + rg * 8 + r;
            if (row < nrows) {
                float4 o;
                upk2(acc[r][0], o.x, o.y);
                upk2(acc[r][1], o.z, o.w);
                *(float4*)&Y[row * DIM + lane * 4] = o;
            }
        }
    }
}

__global__ void __launch_bounds__(256, 2)
k_gemm_single(const float* __restrict__ X,
              const float* __restrict__ W,
              float* __restrict__ Y,
              int nrows) {
    extern __shared__ float sm[];
    float* ws = sm;
    float* xs = sm + DIM * DIM;

    for (int i = threadIdx.x; i < DIM * DIM / 4; i += blockDim.x)
        ((float4*)ws)[i] = ((const float4*)W)[i];

    int lane = threadIdx.x & 31;
    int rg   = threadIdx.x >> 5;

    int ntiles = (nrows + TILE_R - 1) / TILE_R;
    for (int t = blockIdx.x; t < ntiles; t += gridDim.x) {
        int tile = t * TILE_R;
        __syncthreads();
        for (int i = threadIdx.x; i < TILE_R * DIM / 4; i += blockDim.x) {
            int row = i >> 5;
            float4 v = make_float4(0.f, 0.f, 0.f, 0.f);
            if (tile + row < nrows)
                v = ((const float4*)X)[(tile + row) * 32 + (i & 31)];
            ((float4*)xs)[i] = v;
        }
        __syncthreads();

        unsigned long long acc[8][2];
#pragma unroll
        for (int r = 0; r < 8; ++r) { acc[r][0] = 0ull; acc[r][1] = 0ull; }

#pragma unroll 2
        for (int k4 = 0; k4 < DIM; k4 += 4) {
            float4 xa[8];
#pragma unroll
            for (int r = 0; r < 8; ++r)
                xa[r] = *(const float4*)&xs[(rg * 8 + r) * DIM + k4];
#pragma unroll
            for (int kk = 0; kk < 4; ++kk) {
                ulonglong2 wv = *(const ulonglong2*)&ws[(k4 + kk) * DIM + lane * 4];
#pragma unroll
                for (int r = 0; r < 8; ++r) {
                    float x = ((const float*)&xa[r])[kk];
                    unsigned long long xp = pk2(x, x);
                    fma2(acc[r][0], xp, wv.x);
                    fma2(acc[r][1], xp, wv.y);
                }
            }
        }

#pragma unroll
        for (int r = 0; r < 8; ++r) {
            int row = tile + rg * 8 + r;
            if (row < nrows) {
                float4 o;
                upk2(acc[r][0], o.x, o.y);
                upk2(acc[r][1], o.z, o.w);
                *(float4*)&Y[row * DIM + lane * 4] = o;
            }
        }
    }
}

// ================= per-node fused attention + aggregation ====================
// Processes nodes in [node_begin, node_end). One warp per dst node; ILP-2.
__global__ void __launch_bounds__(256)
k_node_agg(const int* __restrict__ rowptr,
           const int* __restrict__ deg,
           const int* __restrict__ perm,
           const float* __restrict__ xl,
           const float* __restrict__ xra,
           const float* __restrict__ xrm,
           const float* __restrict__ att1,
           const float* __restrict__ bias1,
           float* __restrict__ out,
           int node_begin, int node_end) {
    int warp_global = (blockIdx.x * blockDim.x + threadIdx.x) >> 5;
    int lane = threadIdx.x & 31;
    int nwarps = (gridDim.x * blockDim.x) >> 5;

    float4 attv = ((const float4*)att1)[lane];
    float4 bv   = ((const float4*)bias1)[lane];

    for (int node = node_begin + warp_global; node < node_end; node += nwarps) {
        const float* xr = (node < N_A) ? &xra[node * DIM]
                                       : &xrm[(node - N_A) * DIM];
        float4 b = *(const float4*)&xr[lane * 4];

        int start = rowptr[node];
        int len   = deg[node];

        float4 acc = make_float4(0.f, 0.f, 0.f, 0.f);
        float ssum = 0.f;

        for (int base = 0; base < len; base += 32) {
            int e = base + lane;
            int sidx = (e < len) ? perm[start + e] : 0;
            int cnt = min(32, len - base);

            int j = 0;
            for (; j + 2 <= cnt; j += 2) {
                int si0 = __shfl_sync(0xffffffffu, sidx, j);
                int si1 = __shfl_sync(0xffffffffu, sidx, j + 1);
                float4 a0 = *(const float4*)&xl[si0 * DIM + lane * 4];
                float4 a1 = *(const float4*)&xl[si1 * DIM + lane * 4];

                float p0 = lrelu(a0.x + b.x) * attv.x + lrelu(a0.y + b.y) * attv.y
                         + lrelu(a0.z + b.z) * attv.z + lrelu(a0.w + b.w) * attv.w;
                float p1 = lrelu(a1.x + b.x) * attv.x + lrelu(a1.y + b.y) * attv.y
                         + lrelu(a1.z + b.z) * attv.z + lrelu(a1.w + b.w) * attv.w;

                p0 += __shfl_xor_sync(0xffffffffu, p0, 1);
                p1 += __shfl_xor_sync(0xffffffffu, p1, 1);
                p0 += __shfl_xor_sync(0xffffffffu, p0, 2);
                p1 += __shfl_xor_sync(0xffffffffu, p1, 2);
                p0 += __shfl_xor_sync(0xffffffffu, p0, 4);
                p1 += __shfl_xor_sync(0xffffffffu, p1, 4);

                float w0 = __expf(p0);
                float w1 = __expf(p1);

                acc.x = fmaf(w0, a0.x, fmaf(w1, a1.x, acc.x));
                acc.y = fmaf(w0, a0.y, fmaf(w1, a1.y, acc.y));
                acc.z = fmaf(w0, a0.z, fmaf(w1, a1.z, acc.z));
                acc.w = fmaf(w0, a0.w, fmaf(w1, a1.w, acc.w));
                ssum += w0 + w1;
            }
            if (j < cnt) {
                int si = __shfl_sync(0xffffffffu, sidx, j);
                float4 a = *(const float4*)&xl[si * DIM + lane * 4];
                float p = lrelu(a.x + b.x) * attv.x + lrelu(a.y + b.y) * attv.y
                        + lrelu(a.z + b.z) * attv.z + lrelu(a.w + b.w) * attv.w;
                p += __shfl_xor_sync(0xffffffffu, p, 1);
                p += __shfl_xor_sync(0xffffffffu, p, 2);
                p += __shfl_xor_sync(0xffffffffu, p, 4);
                float w = __expf(p);
                acc.x = fmaf(w, a.x, acc.x);
                acc.y = fmaf(w, a.y, acc.y);
                acc.z = fmaf(w, a.z, acc.z);
                acc.w = fmaf(w, a.w, acc.w);
                ssum += w;
            }
        }

        float inv = __frcp_rn(fmaxf(ssum, 1e-16f));
        float4 o = make_float4(fmaf(acc.x, inv, bv.x),
                               fmaf(acc.y, inv, bv.y),
                               fmaf(acc.z, inv, bv.z),
                               fmaf(acc.w, inv, bv.w));
        *(float4*)&out[node * DIM + lane * 4] = o;
    }
}

// ================= host launcher ==============================================
extern "C" void kernel_launch(void* const* d_in, const int* in_sizes, int n_in,
                              void* d_out, int out_size) {
    const float* x_asset  = (const float*)d_in[0];
    const float* x_market = (const float*)d_in[1];
    const int*   edge_aa  = (const int*)d_in[2];
    const int*   edge_am  = (const int*)d_in[3];
    const float* Wl       = (const float*)d_in[4];
    const float* Wr       = (const float*)d_in[5];
    const float* att      = (const float*)d_in[6];
    const float* bias     = (const float*)d_in[7];
    float* out = (float*)d_out;

    // Only the LAST layer matters (x_dict never updated between layers).
    const float* Wl1   = Wl  + DIM * DIM;
    const float* Wr1   = Wr  + DIM * DIM;
    const float* att1  = att + NHEAD * 32;
    const float* bias1 = bias + DIM;

    float *p_xl, *p_xra, *p_xrm;
    int *p_deg, *p_rowptr, *p_cursor, *p_perm;
    cudaGetSymbolAddress((void**)&p_xl,     g_xl);
    cudaGetSymbolAddress((void**)&p_xra,    g_xra);
    cudaGetSymbolAddress((void**)&p_xrm,    g_xrm);
    cudaGetSymbolAddress((void**)&p_deg,    g_deg);
    cudaGetSymbolAddress((void**)&p_rowptr, g_rowptr);
    cudaGetSymbolAddress((void**)&p_cursor, g_cursor);
    cudaGetSymbolAddress((void**)&p_perm,   g_perm);

    cudaFuncSetAttribute(k_gemm_dual,   cudaFuncAttributeMaxDynamicSharedMemorySize, SMEM_DUAL);
    cudaFuncSetAttribute(k_gemm_single, cudaFuncAttributeMaxDynamicSharedMemorySize, SMEM_SINGLE);

    // Lazily-created streams + events (host-side only; identical work each call).
    static cudaStream_t s_csr = nullptr, s_mkt = nullptr;
    static cudaEvent_t ev_fork = nullptr, ev_csr = nullptr,
                       ev_dual = nullptr, ev_mkt = nullptr;
    if (s_csr == nullptr) {
        cudaStreamCreateWithFlags(&s_csr, cudaStreamNonBlocking);
        cudaStreamCreateWithFlags(&s_mkt, cudaStreamNonBlocking);
        cudaEventCreateWithFlags(&ev_fork, cudaEventDisableTiming);
        cudaEventCreateWithFlags(&ev_csr,  cudaEventDisableTiming);
        cudaEventCreateWithFlags(&ev_dual, cudaEventDisableTiming);
        cudaEventCreateWithFlags(&ev_mkt,  cudaEventDisableTiming);
    }

    // --- fork ---
    cudaEventRecord(ev_fork, 0);
    cudaStreamWaitEvent(s_csr, ev_fork, 0);
    cudaStreamWaitEvent(s_mkt, ev_fork, 0);

    // branch 1 (s_csr): CSR build (L2/atomic-bound — hides under dual GEMM)
    cudaMemsetAsync(p_deg, 0, N_TOT * sizeof(int), s_csr);
    k_hist<<<(E_TOT + 255) / 256, 256, 0, s_csr>>>(edge_aa + E_AA,
                                                   edge_am + E_AM, p_deg);
    k_scan<<<1, 1024, 0, s_csr>>>(p_deg, p_rowptr, p_cursor);
    k_scatter<<<(E_TOT + 255) / 256, 256, 0, s_csr>>>(edge_aa, edge_aa + E_AA,
                                                      edge_am, edge_am + E_AM,
                                                      p_cursor, p_perm);
    cudaEventRecord(ev_csr, s_csr);

    // branch 0 (main): dual GEMM (exclusive — FMA-bound, no competition)
    k_gemm_dual<<<148, 512, SMEM_DUAL>>>(x_asset, Wl1, Wr1, p_xl, p_xra, N_A);
    cudaEventRecord(ev_dual, 0);

    // branch 2 (s_mkt): AFTER dual — market GEMM (FMA) co-runs with
    // agg_asset (L2-latency-bound) on main. Complementary pipes.
    cudaStreamWaitEvent(s_mkt, ev_dual, 0);
    k_gemm_single<<<296, 256, SMEM_SINGLE, s_mkt>>>(x_market, Wr1, p_xrm, N_M);
    cudaStreamWaitEvent(s_mkt, ev_csr, 0);
    k_node_agg<<<(N_M * 32 + 255) / 256, 256, 0, s_mkt>>>(p_rowptr, p_deg, p_perm,
                                                          p_xl, p_xra, p_xrm,
                                                          att1, bias1, out,
                                                          N_A, N_TOT);
    cudaEventRecord(ev_mkt, s_mkt);

    // main: asset aggregation (needs dual outputs + CSR)
    cudaStreamWaitEvent(0, ev_csr, 0);
    k_node_agg<<<(N_A * 32 + 255) / 256, 256>>>(p_rowptr, p_deg, p_perm,
                                                p_xl, p_xra, p_xrm,
                                                att1, bias1, out,
                                                0, N_A);

    // --- join onto the capture (main) stream ---
    cudaStreamWaitEvent(0, ev_mkt, 0);
}

// round 15
// speedup vs baseline: 1.1050x; 1.0015x over previous
#include <cuda_runtime.h>
#include <float.h>
#include <stdint.h>

// Problem constants (fixed shapes)
#define N_A   100000
#define N_M   50000
#define N_TOT (N_A + N_M)
#define E_AA  600000
#define E_AM  400000
#define E_TOT (E_AA + E_AM)
#define DIM   128
#define NHEAD 4
#define NEG_SLOPE 0.2f
#define TILE_R 64
#define N_SPLIT (N_A + 12500)   // balanced split of market agg between branches

// ---------------- scratch (device globals) -----------------------------------
__device__ float g_xl [N_A * DIM];     // x_asset @ Wl1
__device__ float g_xra[N_A * DIM];     // x_asset @ Wr1
__device__ float g_xrm[N_M * DIM];     // x_market @ Wr1
__device__ int   g_deg   [N_TOT];
__device__ int   g_rowptr[N_TOT];
__device__ int   g_cursor[N_TOT];
__device__ int   g_perm  [E_TOT];

// ---------------- f32x2 packed math helpers ----------------------------------
__device__ __forceinline__ unsigned long long pk2(float lo, float hi) {
    unsigned long long r;
    asm("mov.b64 %0, {%1, %2};" : "=l"(r) : "f"(lo), "f"(hi));
    return r;
}
__device__ __forceinline__ void fma2(unsigned long long& d,
                                     unsigned long long a, unsigned long long b) {
    asm("fma.rn.f32x2 %0, %1, %2, %0;" : "+l"(d) : "l"(a), "l"(b));
}
__device__ __forceinline__ void upk2(unsigned long long v, float& lo, float& hi) {
    asm("mov.b64 {%0, %1}, %2;" : "=f"(lo), "=f"(hi) : "l"(v));
}

__device__ __forceinline__ float lrelu(float v) {
    return v > 0.0f ? v : NEG_SLOPE * v;
}

// ================= CSR construction ==========================================
__global__ void k_hist(const int* __restrict__ dst_aa,
                       const int* __restrict__ dst_am,
                       int* __restrict__ deg) {
    int i = blockIdx.x * blockDim.x + threadIdx.x;
    if (i < E_AA)            atomicAdd(&deg[dst_aa[i]], 1);
    else if (i < E_TOT)      atomicAdd(&deg[N_A + dst_am[i - E_AA]], 1);
}

// Single-block exclusive scan, 16 ints/thread -> 16384 per chunk, 10 chunks.
__global__ void __launch_bounds__(1024, 1)
k_scan(const int* __restrict__ deg, int* __restrict__ rowptr,
       int* __restrict__ cursor) {
    __shared__ int warpsums[32];
    __shared__ int s_carry;
    int lane = threadIdx.x & 31, wid = threadIdx.x >> 5;
    if (threadIdx.x == 0) s_carry = 0;
    __syncthreads();

    for (int base = 0; base < N_TOT; base += 16384) {
        int idx = base + threadIdx.x * 16;
        int v[16];
        if (idx + 15 < N_TOT) {
#pragma unroll
            for (int q = 0; q < 4; ++q) {
                int4 t = *(const int4*)&deg[idx + q * 4];
                v[q * 4] = t.x; v[q * 4 + 1] = t.y;
                v[q * 4 + 2] = t.z; v[q * 4 + 3] = t.w;
            }
        } else {
#pragma unroll
            for (int q = 0; q < 16; ++q)
                v[q] = (idx + q < N_TOT) ? deg[idx + q] : 0;
        }
        int pre[16];
        int run = 0;
#pragma unroll
        for (int q = 0; q < 16; ++q) { run += v[q]; pre[q] = run; }
        int tsum = run;

        int x = tsum;
#pragma unroll
        for (int o = 1; o < 32; o <<= 1) {
            int y = __shfl_up_sync(0xffffffffu, x, o);
            if (lane >= o) x += y;
        }
        if (lane == 31) warpsums[wid] = x;
        __syncthreads();
        if (wid == 0) {
            int w = warpsums[lane];
#pragma unroll
            for (int o = 1; o < 32; o <<= 1) {
                int y = __shfl_up_sync(0xffffffffu, w, o);
                if (lane >= o) w += y;
            }
            warpsums[lane] = w;
        }
        __syncthreads();

        int carry = s_carry;
        int excl = carry + (wid ? warpsums[wid - 1] : 0) + (x - tsum);
        if (idx + 15 < N_TOT) {
#pragma unroll
            for (int q = 0; q < 4; ++q) {
                int4 o;
                o.x = excl + (q * 4     ? pre[q * 4 - 1] : 0);
                o.y = excl + pre[q * 4];
                o.z = excl + pre[q * 4 + 1];
                o.w = excl + pre[q * 4 + 2];
                *(int4*)&rowptr[idx + q * 4] = o;
                *(int4*)&cursor[idx + q * 4] = o;
            }
        } else {
#pragma unroll
            for (int q = 0; q < 16; ++q) {
                if (idx + q < N_TOT) {
                    int e = excl + (q ? pre[q - 1] : 0);
                    rowptr[idx + q] = e;
                    cursor[idx + q] = e;
                }
            }
        }
        __syncthreads();
        if (threadIdx.x == 0) s_carry = carry + warpsums[31];
        __syncthreads();
    }
}

__global__ void k_scatter(const int* __restrict__ src_aa, const int* __restrict__ dst_aa,
                          const int* __restrict__ src_am, const int* __restrict__ dst_am,
                          int* __restrict__ cursor, int* __restrict__ perm) {
    int i = blockIdx.x * blockDim.x + threadIdx.x;
    if (i < E_AA) {
        int d = dst_aa[i];
        int slot = atomicAdd(&cursor[d], 1);
        perm[slot] = src_aa[i];
    } else if (i < E_TOT) {
        int j = i - E_AA;
        int d = N_A + dst_am[j];
        int slot = atomicAdd(&cursor[d], 1);
        perm[slot] = src_am[j];
    }
}

// ================= GEMMs (R8 configuration — measured best) ===================
#define SMEM_DUAL   ((2 * DIM * DIM + TILE_R * DIM) * (int)sizeof(float))  // 163840
#define SMEM_SINGLE ((DIM * DIM + TILE_R * DIM) * (int)sizeof(float))      //  98304

__global__ void __launch_bounds__(512, 1)
k_gemm_dual(const float* __restrict__ X,
            const float* __restrict__ Wl,
            const float* __restrict__ Wr,
            float* __restrict__ Yl,
            float* __restrict__ Yr,
            int nrows) {
    extern __shared__ float sm[];
    float* wls = sm;                 // [128][128]
    float* wrs = sm + DIM * DIM;
    float* xs  = sm + 2 * DIM * DIM; // [64][128]

    for (int i = threadIdx.x; i < DIM * DIM / 4; i += blockDim.x) {
        ((float4*)wls)[i] = ((const float4*)Wl)[i];
        ((float4*)wrs)[i] = ((const float4*)Wr)[i];
    }

    int lane = threadIdx.x & 31;
    int wid  = threadIdx.x >> 5;
    int half = wid >> 3;             // 0: Wl, 1: Wr
    int rg   = wid & 7;

    const float* ws = half ? wrs : wls;
    float*       Y  = half ? Yr  : Yl;

    int ntiles = (nrows + TILE_R - 1) / TILE_R;
    for (int t = blockIdx.x; t < ntiles; t += gridDim.x) {
        int tile = t * TILE_R;
        __syncthreads();
        for (int i = threadIdx.x; i < TILE_R * DIM / 4; i += blockDim.x) {
            int row = i >> 5;
            float4 v = make_float4(0.f, 0.f, 0.f, 0.f);
            if (tile + row < nrows)
                v = ((const float4*)X)[(tile + row) * 32 + (i & 31)];
            ((float4*)xs)[i] = v;
        }
        __syncthreads();

        unsigned long long acc[8][2];
#pragma unroll
        for (int r = 0; r < 8; ++r) { acc[r][0] = 0ull; acc[r][1] = 0ull; }

#pragma unroll 2
        for (int k4 = 0; k4 < DIM; k4 += 4) {
            float4 xa[8];
#pragma unroll
            for (int r = 0; r < 8; ++r)
                xa[r] = *(const float4*)&xs[(rg * 8 + r) * DIM + k4];
#pragma unroll
            for (int kk = 0; kk < 4; ++kk) {
                ulonglong2 wv = *(const ulonglong2*)&ws[(k4 + kk) * DIM + lane * 4];
#pragma unroll
                for (int r = 0; r < 8; ++r) {
                    float x = ((const float*)&xa[r])[kk];
                    unsigned long long xp = pk2(x, x);
                    fma2(acc[r][0], xp, wv.x);
                    fma2(acc[r][1], xp, wv.y);
                }
            }
        }

#pragma unroll
        for (int r = 0; r < 8; ++r) {
            int row = tile + rg * 8 + r;
            if (row < nrows) {
                float4 o;
                upk2(acc[r][0], o.x, o.y);
                upk2(acc[r][1], o.z, o.w);
                *(float4*)&Y[row * DIM + lane * 4] = o;
            }
        }
    }
}

__global__ void __launch_bounds__(256, 2)
k_gemm_single(const float* __restrict__ X,
              const float* __restrict__ W,
              float* __restrict__ Y,
              int nrows) {
    extern __shared__ float sm[];
    float* ws = sm;
    float* xs = sm + DIM * DIM;

    for (int i = threadIdx.x; i < DIM * DIM / 4; i += blockDim.x)
        ((float4*)ws)[i] = ((const float4*)W)[i];

    int lane = threadIdx.x & 31;
    int rg   = threadIdx.x >> 5;

    int ntiles = (nrows + TILE_R - 1) / TILE_R;
    for (int t = blockIdx.x; t < ntiles; t += gridDim.x) {
        int tile = t * TILE_R;
        __syncthreads();
        for (int i = threadIdx.x; i < TILE_R * DIM / 4; i += blockDim.x) {
            int row = i >> 5;
            float4 v = make_float4(0.f, 0.f, 0.f, 0.f);
            if (tile + row < nrows)
                v = ((const float4*)X)[(tile + row) * 32 + (i & 31)];
            ((float4*)xs)[i] = v;
        }
        __syncthreads();

        unsigned long long acc[8][2];
#pragma unroll
        for (int r = 0; r < 8; ++r) { acc[r][0] = 0ull; acc[r][1] = 0ull; }

#pragma unroll 2
        for (int k4 = 0; k4 < DIM; k4 += 4) {
            float4 xa[8];
#pragma unroll
            for (int r = 0; r < 8; ++r)
                xa[r] = *(const float4*)&xs[(rg * 8 + r) * DIM + k4];
#pragma unroll
            for (int kk = 0; kk < 4; ++kk) {
                ulonglong2 wv = *(const ulonglong2*)&ws[(k4 + kk) * DIM + lane * 4];
#pragma unroll
                for (int r = 0; r < 8; ++r) {
                    float x = ((const float*)&xa[r])[kk];
                    unsigned long long xp = pk2(x, x);
                    fma2(acc[r][0], xp, wv.x);
                    fma2(acc[r][1], xp, wv.y);
                }
            }
        }

#pragma unroll
        for (int r = 0; r < 8; ++r) {
            int row = tile + rg * 8 + r;
            if (row < nrows) {
                float4 o;
                upk2(acc[r][0], o.x, o.y);
                upk2(acc[r][1], o.z, o.w);
                *(float4*)&Y[row * DIM + lane * 4] = o;
            }
        }
    }
}

// ================= per-node fused attention + aggregation ====================
// Processes nodes in [node_begin, node_end). One warp per dst node; ILP-2.
__global__ void __launch_bounds__(256)
k_node_agg(const int* __restrict__ rowptr,
           const int* __restrict__ deg,
           const int* __restrict__ perm,
           const float* __restrict__ xl,
           const float* __restrict__ xra,
           const float* __restrict__ xrm,
           const float* __restrict__ att1,
           const float* __restrict__ bias1,
           float* __restrict__ out,
           int node_begin, int node_end) {
    int warp_global = (blockIdx.x * blockDim.x + threadIdx.x) >> 5;
    int lane = threadIdx.x & 31;
    int nwarps = (gridDim.x * blockDim.x) >> 5;

    float4 attv = ((const float4*)att1)[lane];
    float4 bv   = ((const float4*)bias1)[lane];

    for (int node = node_begin + warp_global; node < node_end; node += nwarps) {
        const float* xr = (node < N_A) ? &xra[node * DIM]
                                       : &xrm[(node - N_A) * DIM];
        float4 b = *(const float4*)&xr[lane * 4];

        int start = rowptr[node];
        int len   = deg[node];

        float4 acc = make_float4(0.f, 0.f, 0.f, 0.f);
        float ssum = 0.f;

        for (int base = 0; base < len; base += 32) {
            int e = base + lane;
            int sidx = (e < len) ? perm[start + e] : 0;
            int cnt = min(32, len - base);

            int j = 0;
            for (; j + 2 <= cnt; j += 2) {
                int si0 = __shfl_sync(0xffffffffu, sidx, j);
                int si1 = __shfl_sync(0xffffffffu, sidx, j + 1);
                float4 a0 = *(const float4*)&xl[si0 * DIM + lane * 4];
                float4 a1 = *(const float4*)&xl[si1 * DIM + lane * 4];

                float p0 = lrelu(a0.x + b.x) * attv.x + lrelu(a0.y + b.y) * attv.y
                         + lrelu(a0.z + b.z) * attv.z + lrelu(a0.w + b.w) * attv.w;
                float p1 = lrelu(a1.x + b.x) * attv.x + lrelu(a1.y + b.y) * attv.y
                         + lrelu(a1.z + b.z) * attv.z + lrelu(a1.w + b.w) * attv.w;

                p0 += __shfl_xor_sync(0xffffffffu, p0, 1);
                p1 += __shfl_xor_sync(0xffffffffu, p1, 1);
                p0 += __shfl_xor_sync(0xffffffffu, p0, 2);
                p1 += __shfl_xor_sync(0xffffffffu, p1, 2);
                p0 += __shfl_xor_sync(0xffffffffu, p0, 4);
                p1 += __shfl_xor_sync(0xffffffffu, p1, 4);

                float w0 = __expf(p0);
                float w1 = __expf(p1);

                acc.x = fmaf(w0, a0.x, fmaf(w1, a1.x, acc.x));
                acc.y = fmaf(w0, a0.y, fmaf(w1, a1.y, acc.y));
                acc.z = fmaf(w0, a0.z, fmaf(w1, a1.z, acc.z));
                acc.w = fmaf(w0, a0.w, fmaf(w1, a1.w, acc.w));
                ssum += w0 + w1;
            }
            if (j < cnt) {
                int si = __shfl_sync(0xffffffffu, sidx, j);
                float4 a = *(const float4*)&xl[si * DIM + lane * 4];
                float p = lrelu(a.x + b.x) * attv.x + lrelu(a.y + b.y) * attv.y
                        + lrelu(a.z + b.z) * attv.z + lrelu(a.w + b.w) * attv.w;
                p += __shfl_xor_sync(0xffffffffu, p, 1);
                p += __shfl_xor_sync(0xffffffffu, p, 2);
                p += __shfl_xor_sync(0xffffffffu, p, 4);
                float w = __expf(p);
                acc.x = fmaf(w, a.x, acc.x);
                acc.y = fmaf(w, a.y, acc.y);
                acc.z = fmaf(w, a.z, acc.z);
                acc.w = fmaf(w, a.w, acc.w);
                ssum += w;
            }
        }

        float inv = __frcp_rn(fmaxf(ssum, 1e-16f));
        float4 o = make_float4(fmaf(acc.x, inv, bv.x),
                               fmaf(acc.y, inv, bv.y),
                               fmaf(acc.z, inv, bv.z),
                               fmaf(acc.w, inv, bv.w));
        *(float4*)&out[node * DIM + lane * 4] = o;
    }
}

// ================= host launcher ==============================================
extern "C" void kernel_launch(void* const* d_in, const int* in_sizes, int n_in,
                              void* d_out, int out_size) {
    const float* x_asset  = (const float*)d_in[0];
    const float* x_market = (const float*)d_in[1];
    const int*   edge_aa  = (const int*)d_in[2];
    const int*   edge_am  = (const int*)d_in[3];
    const float* Wl       = (const float*)d_in[4];
    const float* Wr       = (const float*)d_in[5];
    const float* att      = (const float*)d_in[6];
    const float* bias     = (const float*)d_in[7];
    float* out = (float*)d_out;

    // Only the LAST layer matters (x_dict never updated between layers).
    const float* Wl1   = Wl  + DIM * DIM;
    const float* Wr1   = Wr  + DIM * DIM;
    const float* att1  = att + NHEAD * 32;
    const float* bias1 = bias + DIM;

    float *p_xl, *p_xra, *p_xrm;
    int *p_deg, *p_rowptr, *p_cursor, *p_perm;
    cudaGetSymbolAddress((void**)&p_xl,     g_xl);
    cudaGetSymbolAddress((void**)&p_xra,    g_xra);
    cudaGetSymbolAddress((void**)&p_xrm,    g_xrm);
    cudaGetSymbolAddress((void**)&p_deg,    g_deg);
    cudaGetSymbolAddress((void**)&p_rowptr, g_rowptr);
    cudaGetSymbolAddress((void**)&p_cursor, g_cursor);
    cudaGetSymbolAddress((void**)&p_perm,   g_perm);

    cudaFuncSetAttribute(k_gemm_dual,   cudaFuncAttributeMaxDynamicSharedMemorySize, SMEM_DUAL);
    cudaFuncSetAttribute(k_gemm_single, cudaFuncAttributeMaxDynamicSharedMemorySize, SMEM_SINGLE);

    // Lazily-created streams + events (host-side only; identical work each call).
    static cudaStream_t s_csr = nullptr, s_mkt = nullptr;
    static cudaEvent_t ev_fork = nullptr, ev_csr = nullptr,
                       ev_dual = nullptr, ev_single = nullptr, ev_mkt = nullptr;
    if (s_csr == nullptr) {
        cudaStreamCreateWithFlags(&s_csr, cudaStreamNonBlocking);
        cudaStreamCreateWithFlags(&s_mkt, cudaStreamNonBlocking);
        cudaEventCreateWithFlags(&ev_fork,   cudaEventDisableTiming);
        cudaEventCreateWithFlags(&ev_csr,    cudaEventDisableTiming);
        cudaEventCreateWithFlags(&ev_dual,   cudaEventDisableTiming);
        cudaEventCreateWithFlags(&ev_single, cudaEventDisableTiming);
        cudaEventCreateWithFlags(&ev_mkt,    cudaEventDisableTiming);
    }

    // --- fork ---
    cudaEventRecord(ev_fork, 0);
    cudaStreamWaitEvent(s_csr, ev_fork, 0);
    cudaStreamWaitEvent(s_mkt, ev_fork, 0);

    // branch 1 (s_csr): CSR build (L2/atomic-bound — hides under dual GEMM)
    cudaMemsetAsync(p_deg, 0, N_TOT * sizeof(int), s_csr);
    k_hist<<<(E_TOT + 255) / 256, 256, 0, s_csr>>>(edge_aa + E_AA,
                                                   edge_am + E_AM, p_deg);
    k_scan<<<1, 1024, 0, s_csr>>>(p_deg, p_rowptr, p_cursor);
    k_scatter<<<(E_TOT + 255) / 256, 256, 0, s_csr>>>(edge_aa, edge_aa + E_AA,
                                                      edge_am, edge_am + E_AM,
                                                      p_cursor, p_perm);
    cudaEventRecord(ev_csr, s_csr);

    // branch 0 (main): dual GEMM (exclusive)
    k_gemm_dual<<<148, 512, SMEM_DUAL>>>(x_asset, Wl1, Wr1, p_xl, p_xra, N_A);
    cudaEventRecord(ev_dual, 0);

    // branch 2 (s_mkt): after dual — market GEMM, then its share of market agg
    cudaStreamWaitEvent(s_mkt, ev_dual, 0);
    k_gemm_single<<<296, 256, SMEM_SINGLE, s_mkt>>>(x_market, Wr1, p_xrm, N_M);
    cudaEventRecord(ev_single, s_mkt);
    cudaStreamWaitEvent(s_mkt, ev_csr, 0);
    k_node_agg<<<((N_TOT - N_SPLIT) * 32 + 255) / 256, 256, 0, s_mkt>>>(
        p_rowptr, p_deg, p_perm, p_xl, p_xra, p_xrm,
        att1, bias1, out, N_SPLIT, N_TOT);
    cudaEventRecord(ev_mkt, s_mkt);

    // main: asset agg, then (after single GEMM lands) its share of market agg
    cudaStreamWaitEvent(0, ev_csr, 0);
    k_node_agg<<<(N_A * 32 + 255) / 256, 256>>>(p_rowptr, p_deg, p_perm,
                                                p_xl, p_xra, p_xrm,
                                                att1, bias1, out,
                                                0, N_A);
    cudaStreamWaitEvent(0, ev_single, 0);
    k_node_agg<<<((N_SPLIT - N_A) * 32 + 255) / 256, 256>>>(
        p_rowptr, p_deg, p_perm, p_xl, p_xra, p_xrm,
        att1, bias1, out, N_A, N_SPLIT);

    // --- join onto the capture (main) stream ---
    cudaStreamWaitEvent(0, ev_mkt, 0);
}

// round 16
// speedup vs baseline: 1.1198x; 1.0134x over previous
#include <cuda_runtime.h>
#include <cuda_fp16.h>
#include <float.h>
#include <stdint.h>

// Problem constants (fixed shapes)
#define N_A   100000
#define N_M   50000
#define N_TOT (N_A + N_M)
#define E_AA  600000
#define E_AM  400000
#define E_TOT (E_AA + E_AM)
#define DIM   128
#define NHEAD 4
#define NEG_SLOPE 0.2f
#define TILE_R 64
#define N_SPLIT (N_A + 12500)   // balanced split of market agg between branches

// ---------------- scratch (device globals) -----------------------------------
__device__ __half g_xlh[N_A * DIM];    // x_asset @ Wl1 (fp16 — gather-only)
__device__ float  g_xra[N_A * DIM];    // x_asset @ Wr1
__device__ float  g_xrm[N_M * DIM];    // x_market @ Wr1
__device__ int    g_deg   [N_TOT];
__device__ int    g_rowptr[N_TOT];
__device__ int    g_cursor[N_TOT];
__device__ int    g_perm  [E_TOT];

// ---------------- f32x2 packed math helpers ----------------------------------
__device__ __forceinline__ unsigned long long pk2(float lo, float hi) {
    unsigned long long r;
    asm("mov.b64 %0, {%1, %2};" : "=l"(r) : "f"(lo), "f"(hi));
    return r;
}
__device__ __forceinline__ void fma2(unsigned long long& d,
                                     unsigned long long a, unsigned long long b) {
    asm("fma.rn.f32x2 %0, %1, %2, %0;" : "+l"(d) : "l"(a), "l"(b));
}
__device__ __forceinline__ void upk2(unsigned long long v, float& lo, float& hi) {
    asm("mov.b64 {%0, %1}, %2;" : "=f"(lo), "=f"(hi) : "l"(v));
}

__device__ __forceinline__ float lrelu(float v) {
    return v > 0.0f ? v : NEG_SLOPE * v;
}

// ================= CSR construction ==========================================
__global__ void k_hist(const int* __restrict__ dst_aa,
                       const int* __restrict__ dst_am,
                       int* __restrict__ deg) {
    int i = blockIdx.x * blockDim.x + threadIdx.x;
    if (i < E_AA)            atomicAdd(&deg[dst_aa[i]], 1);
    else if (i < E_TOT)      atomicAdd(&deg[N_A + dst_am[i - E_AA]], 1);
}

// Single-block exclusive scan, 16 ints/thread -> 16384 per chunk, 10 chunks.
__global__ void __launch_bounds__(1024, 1)
k_scan(const int* __restrict__ deg, int* __restrict__ rowptr,
       int* __restrict__ cursor) {
    __shared__ int warpsums[32];
    __shared__ int s_carry;
    int lane = threadIdx.x & 31, wid = threadIdx.x >> 5;
    if (threadIdx.x == 0) s_carry = 0;
    __syncthreads();

    for (int base = 0; base < N_TOT; base += 16384) {
        int idx = base + threadIdx.x * 16;
        int v[16];
        if (idx + 15 < N_TOT) {
#pragma unroll
            for (int q = 0; q < 4; ++q) {
                int4 t = *(const int4*)&deg[idx + q * 4];
                v[q * 4] = t.x; v[q * 4 + 1] = t.y;
                v[q * 4 + 2] = t.z; v[q * 4 + 3] = t.w;
            }
        } else {
#pragma unroll
            for (int q = 0; q < 16; ++q)
                v[q] = (idx + q < N_TOT) ? deg[idx + q] : 0;
        }
        int pre[16];
        int run = 0;
#pragma unroll
        for (int q = 0; q < 16; ++q) { run += v[q]; pre[q] = run; }
        int tsum = run;

        int x = tsum;
#pragma unroll
        for (int o = 1; o < 32; o <<= 1) {
            int y = __shfl_up_sync(0xffffffffu, x, o);
            if (lane >= o) x += y;
        }
        if (lane == 31) warpsums[wid] = x;
        __syncthreads();
        if (wid == 0) {
            int w = warpsums[lane];
#pragma unroll
            for (int o = 1; o < 32; o <<= 1) {
                int y = __shfl_up_sync(0xffffffffu, w, o);
                if (lane >= o) w += y;
            }
            warpsums[lane] = w;
        }
        __syncthreads();

        int carry = s_carry;
        int excl = carry + (wid ? warpsums[wid - 1] : 0) + (x - tsum);
        if (idx + 15 < N_TOT) {
#pragma unroll
            for (int q = 0; q < 4; ++q) {
                int4 o;
                o.x = excl + (q * 4     ? pre[q * 4 - 1] : 0);
                o.y = excl + pre[q * 4];
                o.z = excl + pre[q * 4 + 1];
                o.w = excl + pre[q * 4 + 2];
                *(int4*)&rowptr[idx + q * 4] = o;
                *(int4*)&cursor[idx + q * 4] = o;
            }
        } else {
#pragma unroll
            for (int q = 0; q < 16; ++q) {
                if (idx + q < N_TOT) {
                    int e = excl + (q ? pre[q - 1] : 0);
                    rowptr[idx + q] = e;
                    cursor[idx + q] = e;
                }
            }
        }
        __syncthreads();
        if (threadIdx.x == 0) s_carry = carry + warpsums[31];
        __syncthreads();
    }
}

__global__ void k_scatter(const int* __restrict__ src_aa, const int* __restrict__ dst_aa,
                          const int* __restrict__ src_am, const int* __restrict__ dst_am,
                          int* __restrict__ cursor, int* __restrict__ perm) {
    int i = blockIdx.x * blockDim.x + threadIdx.x;
    if (i < E_AA) {
        int d = dst_aa[i];
        int slot = atomicAdd(&cursor[d], 1);
        perm[slot] = src_aa[i];
    } else if (i < E_TOT) {
        int j = i - E_AA;
        int d = N_A + dst_am[j];
        int slot = atomicAdd(&cursor[d], 1);
        perm[slot] = src_am[j];
    }
}

// ================= GEMMs (R8 config; xl emitted as fp16) ======================
#define SMEM_DUAL   ((2 * DIM * DIM + TILE_R * DIM) * (int)sizeof(float))  // 163840
#define SMEM_SINGLE ((DIM * DIM + TILE_R * DIM) * (int)sizeof(float))      //  98304

__global__ void __launch_bounds__(512, 1)
k_gemm_dual(const float* __restrict__ X,
            const float* __restrict__ Wl,
            const float* __restrict__ Wr,
            __half* __restrict__ Ylh,
            float* __restrict__ Yr,
            int nrows) {
    extern __shared__ float sm[];
    float* wls = sm;                 // [128][128]
    float* wrs = sm + DIM * DIM;
    float* xs  = sm + 2 * DIM * DIM; // [64][128]

    for (int i = threadIdx.x; i < DIM * DIM / 4; i += blockDim.x) {
        ((float4*)wls)[i] = ((const float4*)Wl)[i];
        ((float4*)wrs)[i] = ((const float4*)Wr)[i];
    }

    int lane = threadIdx.x & 31;
    int wid  = threadIdx.x >> 5;
    int half = wid >> 3;             // 0: Wl -> fp16 xl, 1: Wr -> fp32 xra
    int rg   = wid & 7;

    const float* ws = half ? wrs : wls;

    int ntiles = (nrows + TILE_R - 1) / TILE_R;
    for (int t = blockIdx.x; t < ntiles; t += gridDim.x) {
        int tile = t * TILE_R;
        __syncthreads();
        for (int i = threadIdx.x; i < TILE_R * DIM / 4; i += blockDim.x) {
            int row = i >> 5;
            float4 v = make_float4(0.f, 0.f, 0.f, 0.f);
            if (tile + row < nrows)
                v = ((const float4*)X)[(tile + row) * 32 + (i & 31)];
            ((float4*)xs)[i] = v;
        }
        __syncthreads();

        unsigned long long acc[8][2];
#pragma unroll
        for (int r = 0; r < 8; ++r) { acc[r][0] = 0ull; acc[r][1] = 0ull; }

#pragma unroll 2
        for (int k4 = 0; k4 < DIM; k4 += 4) {
            float4 xa[8];
#pragma unroll
            for (int r = 0; r < 8; ++r)
                xa[r] = *(const float4*)&xs[(rg * 8 + r) * DIM + k4];
#pragma unroll
            for (int kk = 0; kk < 4; ++kk) {
                ulonglong2 wv = *(const ulonglong2*)&ws[(k4 + kk) * DIM + lane * 4];
#pragma unroll
                for (int r = 0; r < 8; ++r) {
                    float x = ((const float*)&xa[r])[kk];
                    unsigned long long xp = pk2(x, x);
                    fma2(acc[r][0], xp, wv.x);
                    fma2(acc[r][1], xp, wv.y);
                }
            }
        }

#pragma unroll
        for (int r = 0; r < 8; ++r) {
            int row = tile + rg * 8 + r;
            if (row < nrows) {
                float4 o;
                upk2(acc[r][0], o.x, o.y);
                upk2(acc[r][1], o.z, o.w);
                if (half) {
                    *(float4*)&Yr[row * DIM + lane * 4] = o;
                } else {
                    __half2 h01 = __floats2half2_rn(o.x, o.y);
                    __half2 h23 = __floats2half2_rn(o.z, o.w);
                    uint2 packed;
                    packed.x = *(uint32_t*)&h01;
                    packed.y = *(uint32_t*)&h23;
                    *(uint2*)&Ylh[row * DIM + lane * 4] = packed;
                }
            }
        }
    }
}

__global__ void __launch_bounds__(256, 2)
k_gemm_single(const float* __restrict__ X,
              const float* __restrict__ W,
              float* __restrict__ Y,
              int nrows) {
    extern __shared__ float sm[];
    float* ws = sm;
    float* xs = sm + DIM * DIM;

    for (int i = threadIdx.x; i < DIM * DIM / 4; i += blockDim.x)
        ((float4*)ws)[i] = ((const float4*)W)[i];

    int lane = threadIdx.x & 31;
    int rg   = threadIdx.x >> 5;

    int ntiles = (nrows + TILE_R - 1) / TILE_R;
    for (int t = blockIdx.x; t < ntiles; t += gridDim.x) {
        int tile = t * TILE_R;
        __syncthreads();
        for (int i = threadIdx.x; i < TILE_R * DIM / 4; i += blockDim.x) {
            int row = i >> 5;
            float4 v = make_float4(0.f, 0.f, 0.f, 0.f);
            if (tile + row < nrows)
                v = ((const float4*)X)[(tile + row) * 32 + (i & 31)];
            ((float4*)xs)[i] = v;
        }
        __syncthreads();

        unsigned long long acc[8][2];
#pragma unroll
        for (int r = 0; r < 8; ++r) { acc[r][0] = 0ull; acc[r][1] = 0ull; }

#pragma unroll 2
        for (int k4 = 0; k4 < DIM; k4 += 4) {
            float4 xa[8];
#pragma unroll
            for (int r = 0; r < 8; ++r)
                xa[r] = *(const float4*)&xs[(rg * 8 + r) * DIM + k4];
#pragma unroll
            for (int kk = 0; kk < 4; ++kk) {
                ulonglong2 wv = *(const ulonglong2*)&ws[(k4 + kk) * DIM + lane * 4];
#pragma unroll
                for (int r = 0; r < 8; ++r) {
                    float x = ((const float*)&xa[r])[kk];
                    unsigned long long xp = pk2(x, x);
                    fma2(acc[r][0], xp, wv.x);
                    fma2(acc[r][1], xp, wv.y);
                }
            }
        }

#pragma unroll
        for (int r = 0; r < 8; ++r) {
            int row = tile + rg * 8 + r;
            if (row < nrows) {
                float4 o;
                upk2(acc[r][0], o.x, o.y);
                upk2(acc[r][1], o.z, o.w);
                *(float4*)&Y[row * DIM + lane * 4] = o;
            }
        }
    }
}

// ================= per-node fused attention + aggregation ====================
// fp16 xl gathers (8B/lane); everything else fp32. ILP-2.
__device__ __forceinline__ float4 ld_xl_h4(const __half* xlh, int si, int lane) {
    uint2 raw = *(const uint2*)&xlh[si * DIM + lane * 4];
    __half2 h01 = *(__half2*)&raw.x;
    __half2 h23 = *(__half2*)&raw.y;
    float2 f01 = __half22float2(h01);
    float2 f23 = __half22float2(h23);
    return make_float4(f01.x, f01.y, f23.x, f23.y);
}

__global__ void __launch_bounds__(256)
k_node_agg(const int* __restrict__ rowptr,
           const int* __restrict__ deg,
           const int* __restrict__ perm,
           const __half* __restrict__ xlh,
           const float* __restrict__ xra,
           const float* __restrict__ xrm,
           const float* __restrict__ att1,
           const float* __restrict__ bias1,
           float* __restrict__ out,
           int node_begin, int node_end) {
    int warp_global = (blockIdx.x * blockDim.x + threadIdx.x) >> 5;
    int lane = threadIdx.x & 31;
    int nwarps = (gridDim.x * blockDim.x) >> 5;

    float4 attv = ((const float4*)att1)[lane];
    float4 bv   = ((const float4*)bias1)[lane];

    for (int node = node_begin + warp_global; node < node_end; node += nwarps) {
        const float* xr = (node < N_A) ? &xra[node * DIM]
                                       : &xrm[(node - N_A) * DIM];
        float4 b = *(const float4*)&xr[lane * 4];

        int start = rowptr[node];
        int len   = deg[node];

        float4 acc = make_float4(0.f, 0.f, 0.f, 0.f);
        float ssum = 0.f;

        for (int base = 0; base < len; base += 32) {
            int e = base + lane;
            int sidx = (e < len) ? perm[start + e] : 0;
            int cnt = min(32, len - base);

            int j = 0;
            for (; j + 2 <= cnt; j += 2) {
                int si0 = __shfl_sync(0xffffffffu, sidx, j);
                int si1 = __shfl_sync(0xffffffffu, sidx, j + 1);
                float4 a0 = ld_xl_h4(xlh, si0, lane);
                float4 a1 = ld_xl_h4(xlh, si1, lane);

                float p0 = lrelu(a0.x + b.x) * attv.x + lrelu(a0.y + b.y) * attv.y
                         + lrelu(a0.z + b.z) * attv.z + lrelu(a0.w + b.w) * attv.w;
                float p1 = lrelu(a1.x + b.x) * attv.x + lrelu(a1.y + b.y) * attv.y
                         + lrelu(a1.z + b.z) * attv.z + lrelu(a1.w + b.w) * attv.w;

                p0 += __shfl_xor_sync(0xffffffffu, p0, 1);
                p1 += __shfl_xor_sync(0xffffffffu, p1, 1);
                p0 += __shfl_xor_sync(0xffffffffu, p0, 2);
                p1 += __shfl_xor_sync(0xffffffffu, p1, 2);
                p0 += __shfl_xor_sync(0xffffffffu, p0, 4);
                p1 += __shfl_xor_sync(0xffffffffu, p1, 4);

                float w0 = __expf(p0);
                float w1 = __expf(p1);

                acc.x = fmaf(w0, a0.x, fmaf(w1, a1.x, acc.x));
                acc.y = fmaf(w0, a0.y, fmaf(w1, a1.y, acc.y));
                acc.z = fmaf(w0, a0.z, fmaf(w1, a1.z, acc.z));
                acc.w = fmaf(w0, a0.w, fmaf(w1, a1.w, acc.w));
                ssum += w0 + w1;
            }
            if (j < cnt) {
                int si = __shfl_sync(0xffffffffu, sidx, j);
                float4 a = ld_xl_h4(xlh, si, lane);
                float p = lrelu(a.x + b.x) * attv.x + lrelu(a.y + b.y) * attv.y
                        + lrelu(a.z + b.z) * attv.z + lrelu(a.w + b.w) * attv.w;
                p += __shfl_xor_sync(0xffffffffu, p, 1);
                p += __shfl_xor_sync(0xffffffffu, p, 2);
                p += __shfl_xor_sync(0xffffffffu, p, 4);
                float w = __expf(p);
                acc.x = fmaf(w, a.x, acc.x);
                acc.y = fmaf(w, a.y, acc.y);
                acc.z = fmaf(w, a.z, acc.z);
                acc.w = fmaf(w, a.w, acc.w);
                ssum += w;
            }
        }

        float inv = __frcp_rn(fmaxf(ssum, 1e-16f));
        float4 o = make_float4(fmaf(acc.x, inv, bv.x),
                               fmaf(acc.y, inv, bv.y),
                               fmaf(acc.z, inv, bv.z),
                               fmaf(acc.w, inv, bv.w));
        *(float4*)&out[node * DIM + lane * 4] = o;
    }
}

// ================= host launcher ==============================================
extern "C" void kernel_launch(void* const* d_in, const int* in_sizes, int n_in,
                              void* d_out, int out_size) {
    const float* x_asset  = (const float*)d_in[0];
    const float* x_market = (const float*)d_in[1];
    const int*   edge_aa  = (const int*)d_in[2];
    const int*   edge_am  = (const int*)d_in[3];
    const float* Wl       = (const float*)d_in[4];
    const float* Wr       = (const float*)d_in[5];
    const float* att      = (const float*)d_in[6];
    const float* bias     = (const float*)d_in[7];
    float* out = (float*)d_out;

    // Only the LAST layer matters (x_dict never updated between layers).
    const float* Wl1   = Wl  + DIM * DIM;
    const float* Wr1   = Wr  + DIM * DIM;
    const float* att1  = att + NHEAD * 32;
    const float* bias1 = bias + DIM;

    __half* p_xlh;
    float *p_xra, *p_xrm;
    int *p_deg, *p_rowptr, *p_cursor, *p_perm;
    cudaGetSymbolAddress((void**)&p_xlh,    g_xlh);
    cudaGetSymbolAddress((void**)&p_xra,    g_xra);
    cudaGetSymbolAddress((void**)&p_xrm,    g_xrm);
    cudaGetSymbolAddress((void**)&p_deg,    g_deg);
    cudaGetSymbolAddress((void**)&p_rowptr, g_rowptr);
    cudaGetSymbolAddress((void**)&p_cursor, g_cursor);
    cudaGetSymbolAddress((void**)&p_perm,   g_perm);

    cudaFuncSetAttribute(k_gemm_dual,   cudaFuncAttributeMaxDynamicSharedMemorySize, SMEM_DUAL);
    cudaFuncSetAttribute(k_gemm_single, cudaFuncAttributeMaxDynamicSharedMemorySize, SMEM_SINGLE);

    // Lazily-created streams + events (host-side only; identical work each call).
    static cudaStream_t s_csr = nullptr, s_mkt = nullptr;
    static cudaEvent_t ev_fork = nullptr, ev_csr = nullptr,
                       ev_dual = nullptr, ev_single = nullptr, ev_mkt = nullptr;
    if (s_csr == nullptr) {
        cudaStreamCreateWithFlags(&s_csr, cudaStreamNonBlocking);
        cudaStreamCreateWithFlags(&s_mkt, cudaStreamNonBlocking);
        cudaEventCreateWithFlags(&ev_fork,   cudaEventDisableTiming);
        cudaEventCreateWithFlags(&ev_csr,    cudaEventDisableTiming);
        cudaEventCreateWithFlags(&ev_dual,   cudaEventDisableTiming);
        cudaEventCreateWithFlags(&ev_single, cudaEventDisableTiming);
        cudaEventCreateWithFlags(&ev_mkt,    cudaEventDisableTiming);
    }

    // --- fork ---
    cudaEventRecord(ev_fork, 0);
    cudaStreamWaitEvent(s_csr, ev_fork, 0);
    cudaStreamWaitEvent(s_mkt, ev_fork, 0);

    // branch 1 (s_csr): CSR build (L2/atomic-bound — hides under dual GEMM)
    cudaMemsetAsync(p_deg, 0, N_TOT * sizeof(int), s_csr);
    k_hist<<<(E_TOT + 255) / 256, 256, 0, s_csr>>>(edge_aa + E_AA,
                                                   edge_am + E_AM, p_deg);
    k_scan<<<1, 1024, 0, s_csr>>>(p_deg, p_rowptr, p_cursor);
    k_scatter<<<(E_TOT + 255) / 256, 256, 0, s_csr>>>(edge_aa, edge_aa + E_AA,
                                                      edge_am, edge_am + E_AM,
                                                      p_cursor, p_perm);
    cudaEventRecord(ev_csr, s_csr);

    // branch 0 (main): dual GEMM (exclusive)
    k_gemm_dual<<<148, 512, SMEM_DUAL>>>(x_asset, Wl1, Wr1, p_xlh, p_xra, N_A);
    cudaEventRecord(ev_dual, 0);

    // branch 2 (s_mkt): after dual — market GEMM, then its share of market agg
    cudaStreamWaitEvent(s_mkt, ev_dual, 0);
    k_gemm_single<<<296, 256, SMEM_SINGLE, s_mkt>>>(x_market, Wr1, p_xrm, N_M);
    cudaEventRecord(ev_single, s_mkt);
    cudaStreamWaitEvent(s_mkt, ev_csr, 0);
    k_node_agg<<<((N_TOT - N_SPLIT) * 32 + 255) / 256, 256, 0, s_mkt>>>(
        p_rowptr, p_deg, p_perm, p_xlh, p_xra, p_xrm,
        att1, bias1, out, N_SPLIT, N_TOT);
    cudaEventRecord(ev_mkt, s_mkt);

    // main: asset agg, then (after single GEMM lands) its share of market agg
    cudaStreamWaitEvent(0, ev_csr, 0);
    k_node_agg<<<(N_A * 32 + 255) / 256, 256>>>(p_rowptr, p_deg, p_perm,
                                                p_xlh, p_xra, p_xrm,
                                                att1, bias1, out,
                                                0, N_A);
    cudaStreamWaitEvent(0, ev_single, 0);
    k_node_agg<<<((N_SPLIT - N_A) * 32 + 255) / 256, 256>>>(
        p_rowptr, p_deg, p_perm, p_xlh, p_xra, p_xrm,
        att1, bias1, out, N_A, N_SPLIT);

    // --- join onto the capture (main) stream ---
    cudaStreamWaitEvent(0, ev_mkt, 0);
}